// round 11
// baseline (speedup 1.0000x reference)
#include <cuda_runtime.h>
#include <cuda_fp16.h>

#define D       128
#define NMAX    50000
#define CAP     64

#define BM 128
#define BN 64
#define BK 32
#define STAGES 3
#define ASTR 40    // A smem row stride (halfs): 80B -> ldmatrix conflict-free
#define BSTRB 72   // B smem row stride (halfs): 144B -> ldmatrix conflict-free

// Scratch: fp16 feat, fp16 pre-scaled weights [3][128][128], fp16 h_rel,
// fp16 loop message, per-node counters, edge buckets.
__device__ __half   g_feat16[(size_t)NMAX * D];
__device__ __half   g_w16[3 * D * D];
__device__ __half   g_hrel[2ull * NMAX * D];
__device__ __half   g_loop16[(size_t)NMAX * D];
__device__ int      g_cnt[NMAX];
__device__ unsigned g_bucket[(size_t)NMAX * CAP];

static __device__ __forceinline__ void cp16(unsigned d, const void* s, bool pred) {
    asm volatile("cp.async.cg.shared.global [%0], [%1], 16, %2;"
                 :: "r"(d), "l"(s), "r"(pred ? 16 : 0));
}
static __device__ __forceinline__ void cp_commit() {
    asm volatile("cp.async.commit_group;");
}
template <int NN> static __device__ __forceinline__ void cp_wait() {
    asm volatile("cp.async.wait_group %0;" :: "n"(NN));
}

static __device__ __forceinline__ void ldsm_x4(
    unsigned& r0, unsigned& r1, unsigned& r2, unsigned& r3, unsigned addr)
{
    asm volatile("ldmatrix.sync.aligned.m8n8.x4.shared.b16 {%0,%1,%2,%3}, [%4];"
                 : "=r"(r0), "=r"(r1), "=r"(r2), "=r"(r3) : "r"(addr));
}
static __device__ __forceinline__ void ldsm_x4_t(
    unsigned& r0, unsigned& r1, unsigned& r2, unsigned& r3, unsigned addr)
{
    asm volatile("ldmatrix.sync.aligned.m8n8.x4.trans.shared.b16 {%0,%1,%2,%3}, [%4];"
                 : "=r"(r0), "=r"(r1), "=r"(r2), "=r"(r3) : "r"(addr));
}
static __device__ __forceinline__ void mma_f16(
    float c[4], const unsigned a[4], unsigned b0, unsigned b1)
{
    asm volatile(
        "mma.sync.aligned.m16n8k16.row.col.f32.f16.f16.f32 "
        "{%0,%1,%2,%3}, {%4,%5,%6,%7}, {%8,%9}, {%0,%1,%2,%3};"
        : "+f"(c[0]), "+f"(c[1]), "+f"(c[2]), "+f"(c[3])
        : "r"(a[0]), "r"(a[1]), "r"(a[2]), "r"(a[3]), "r"(b0), "r"(b1));
}

// prep: feat -> fp16 (streaming fp32 reads); weights -> pre-scaled fp16
// [W0|W1|loopW]; zero counters. One thread handles 16 feat elements with
// all loads issued up front (MLP=4).
__global__ __launch_bounds__(256) void prep(
    const float* __restrict__ feat,
    const float* __restrict__ weight,
    const float* __restrict__ loopw,
    int N)
{
    const float s = 0.70710678118654752440f;
    int idx = blockIdx.x * blockDim.x + threadIdx.x;
    int featChunks = N * D / 16;     // 16 floats per thread
    if (idx < featChunks) {
        const float* fp = &feat[(size_t)idx * 16];
        float4 v0 = __ldcs((const float4*)fp);
        float4 v1 = __ldcs((const float4*)(fp + 4));
        float4 v2 = __ldcs((const float4*)(fp + 8));
        float4 v3 = __ldcs((const float4*)(fp + 12));
        __half2 h[8];
        h[0] = __floats2half2_rn(v0.x, v0.y);
        h[1] = __floats2half2_rn(v0.z, v0.w);
        h[2] = __floats2half2_rn(v1.x, v1.y);
        h[3] = __floats2half2_rn(v1.z, v1.w);
        h[4] = __floats2half2_rn(v2.x, v2.y);
        h[5] = __floats2half2_rn(v2.z, v2.w);
        h[6] = __floats2half2_rn(v3.x, v3.y);
        h[7] = __floats2half2_rn(v3.z, v3.w);
        *(uint4*)&g_feat16[(size_t)idx * 16]     = *(uint4*)&h[0];
        *(uint4*)&g_feat16[(size_t)idx * 16 + 8] = *(uint4*)&h[4];
    } else if (idx < featChunks + 3 * D * D / 8) {
        int j = idx - featChunks;
        const float* srcp = (j < 2 * D * D / 8)
            ? &weight[(size_t)j * 8]
            : &loopw[(size_t)(j - 2 * D * D / 8) * 8];
        float4 v0 = *(const float4*)srcp;
        float4 v1 = *(const float4*)(srcp + 4);
        __half2 h[4];
        h[0] = __floats2half2_rn(s * v0.x, s * v0.y);
        h[1] = __floats2half2_rn(s * v0.z, s * v0.w);
        h[2] = __floats2half2_rn(s * v1.x, s * v1.y);
        h[3] = __floats2half2_rn(s * v1.z, s * v1.w);
        *(uint4*)&g_w16[(size_t)j * 8] = *(uint4*)h;
    } else if (idx < featChunks + 3 * D * D / 8 + N) {
        g_cnt[idx - featChunks - 3 * D * D / 8] = 0;
    }
}

// Fused kernel:
//   blockIdx.y < 6 : fp16 tensor-core GEMM, 3-stage cp.async pipeline.
//       cb = y>>1 selects weight plane; (y&1) selects 64-col half.
//       cb 0,1: h_rel[cb] (fp16); cb 2: loop message (fp16).
//   blockIdx.y == 6: edge binning (grid-stride), concurrent with GEMM.
__global__ __launch_bounds__(256, 3) void gemm16(
    const int* __restrict__ src,
    const int* __restrict__ dst,
    const int* __restrict__ et,
    int E, int N)
{
    __shared__ __align__(16) __half As[STAGES][BM][ASTR];   // [m][k]
    __shared__ __align__(16) __half Bs[STAGES][BK][BSTRB];  // [k][n]

    const int tid  = threadIdx.x;

    if (blockIdx.y == 6) {
        int stride = gridDim.x * 256;
        for (int e = blockIdx.x * 256 + tid; e < E; e += stride) {
            int s = __ldg(&src[e]);
            int d = __ldg(&dst[e]);
            int r = __ldg(&et[e]);
            int pos = atomicAdd(&g_cnt[d], 1);
            if (pos < CAP) {
                g_bucket[(size_t)d * CAP + pos] = (unsigned)(r * N + s);
            } else {
                const __half2* row =
                    (const __half2*)&g_hrel[((size_t)r * N + (size_t)s) * D];
                __half2* lp = (__half2*)&g_loop16[(size_t)d * D];
                for (int i = 0; i < D / 2; i++)
                    atomicAdd(&lp[i], row[i]);
            }
        }
        return;
    }

    const int lane = tid & 31;
    const int wid  = tid >> 5;
    const int g    = lane >> 2;
    const int t    = lane & 3;
    const int wm   = (wid & 3) * 32;
    const int wn   = (wid >> 2) * 32;
    const int m0   = blockIdx.x * BM;
    const int cb   = blockIdx.y >> 1;
    const int n0   = (blockIdx.y & 1) * BN;

    const __half* Bg = g_w16 + (size_t)cb * D * D;

    const int arow = tid >> 1;
    const int aoff = (tid & 1) * 16;
    const int gm_a = m0 + arow;
    const bool apred = gm_a < N;
    const int brow = tid >> 3;
    const int boff = (tid & 7) * 8;

    const unsigned asA = (unsigned)__cvta_generic_to_shared(&As[0][arow][aoff]);
    const unsigned asB = (unsigned)__cvta_generic_to_shared(&Bs[0][brow][boff]);
    const unsigned aStage = BM * ASTR * 2;
    const unsigned bStage = BK * BSTRB * 2;

    const int a_m = lane & 15, a_k = (lane >> 4) * 8;
    const int b_k = lane & 15, b_n = (lane >> 4) * 8;
    const unsigned asL = (unsigned)__cvta_generic_to_shared(&As[0][wm + a_m][a_k]);
    const unsigned bsL = (unsigned)__cvta_generic_to_shared(&Bs[0][b_k][wn + b_n]);

    float acc[2][4][4];
#pragma unroll
    for (int i = 0; i < 2; i++)
#pragma unroll
        for (int j = 0; j < 4; j++)
#pragma unroll
            for (int q = 0; q < 4; q++) acc[i][j][q] = 0.f;

    auto issue = [&](int p, int st) {
        const __half* gA = &g_feat16[(size_t)gm_a * D + p * BK + aoff];
        cp16(asA + st * aStage, gA, apred);
        cp16(asA + st * aStage + 16, gA + 8, apred);
        const __half* gB = &Bg[(size_t)(p * BK + brow) * D + n0 + boff];
        cp16(asB + st * bStage, gB, true);
        cp_commit();
    };

    issue(0, 0);
    issue(1, 1);

#pragma unroll
    for (int p = 0; p < 4; p++) {
        if (p < 3) { cp_wait<1>(); } else { cp_wait<0>(); }
        __syncthreads();
        if (p < 2) issue(p + 2, (p + 2) % STAGES);

        const int st = p % STAGES;
        const unsigned aB = asL + st * aStage;
        const unsigned bB = bsL + st * bStage;
#pragma unroll
        for (int kk = 0; kk < BK; kk += 16) {
            unsigned a[2][4];
            ldsm_x4(a[0][0], a[0][1], a[0][2], a[0][3], aB + kk * 2);
            ldsm_x4(a[1][0], a[1][1], a[1][2], a[1][3], aB + 16 * ASTR * 2 + kk * 2);
#pragma unroll
            for (int q = 0; q < 2; q++) {
                unsigned bq[4];
                ldsm_x4_t(bq[0], bq[1], bq[2], bq[3],
                          bB + kk * BSTRB * 2 + q * 16 * 2);
                mma_f16(acc[0][2 * q],     a[0], bq[0], bq[1]);
                mma_f16(acc[1][2 * q],     a[1], bq[0], bq[1]);
                mma_f16(acc[0][2 * q + 1], a[0], bq[2], bq[3]);
                mma_f16(acc[1][2 * q + 1], a[1], bq[2], bq[3]);
            }
        }
    }

    __half* dstb = (cb < 2) ? &g_hrel[(size_t)cb * N * D] : g_loop16;
#pragma unroll
    for (int mt = 0; mt < 2; mt++) {
        int gm_lo = m0 + wm + mt * 16 + g;
        int gm_hi = gm_lo + 8;
#pragma unroll
        for (int nt = 0; nt < 4; nt++) {
            int col = n0 + wn + nt * 8 + 2 * t;
            if (gm_lo < N)
                *(__half2*)&dstb[(size_t)gm_lo * D + col] =
                    __floats2half2_rn(acc[mt][nt][0], acc[mt][nt][1]);
            if (gm_hi < N)
                *(__half2*)&dstb[(size_t)gm_hi * D + col] =
                    __floats2half2_rn(acc[mt][nt][2], acc[mt][nt][3]);
        }
    }
}

// Two warps per node: half 0 sums even bucket entries, half 1 odd entries.
// Half 1 deposits its fp32 partial in smem; half 0 folds partner + loop16 +
// bias and is the sole writer of out. Halved dependent chains, 2x warps.
__global__ __launch_bounds__(256) void aggregate(
    const float* __restrict__ bias,
    float* __restrict__ out, int N)
{
    __shared__ float4 partial[4][32];

    const int wid  = threadIdx.x >> 5;
    const int lane = threadIdx.x & 31;
    const int nl   = wid >> 1;          // node slot in block (0..3)
    const int half = wid & 1;
    const int n    = blockIdx.x * 4 + nl;
    const bool valid = n < N;

    float4 acc = make_float4(0.f, 0.f, 0.f, 0.f);
    if (valid) {
        int cnt = __ldg(&g_cnt[n]);
        if (cnt > CAP) cnt = CAP;
        const unsigned* bk = &g_bucket[(size_t)n * CAP];
#pragma unroll 4
        for (int j = half; j < cnt; j += 2) {
            unsigned idx = __ldcs(&bk[j]);
            uint2 hv = __ldg((const uint2*)&g_hrel[(size_t)idx * D + lane * 4]);
            float2 f0 = __half22float2(*(__half2*)&hv.x);
            float2 f1 = __half22float2(*(__half2*)&hv.y);
            acc.x += f0.x; acc.y += f0.y; acc.z += f1.x; acc.w += f1.y;
        }
    }
    if (half == 1) partial[nl][lane] = acc;
    __syncthreads();
    if (half == 0 && valid) {
        float4 p = partial[nl][lane];
        uint2 lv = __ldg((const uint2*)&g_loop16[(size_t)n * D + lane * 4]);
        float2 l0 = __half22float2(*(__half2*)&lv.x);
        float2 l1 = __half22float2(*(__half2*)&lv.y);
        float4 bv = __ldg((const float4*)&bias[lane * 4]);
        float4 r;
        r.x = acc.x + p.x + l0.x + bv.x;
        r.y = acc.y + p.y + l0.y + bv.y;
        r.z = acc.z + p.z + l1.x + bv.z;
        r.w = acc.w + p.w + l1.y + bv.w;
        __stcs((float4*)&out[(size_t)n * D + lane * 4], r);
    }
}

extern "C" void kernel_launch(void* const* d_in, const int* in_sizes, int n_in,
                              void* d_out, int out_size) {
    const float* feat   = (const float*)d_in[0];
    const int*   src    = (const int*)d_in[1];
    const int*   dst    = (const int*)d_in[2];
    const int*   etypes = (const int*)d_in[3];
    const float* weight = (const float*)d_in[4];
    const float* loopw  = (const float*)d_in[5];
    const float* bias   = (const float*)d_in[6];
    float* out = (float*)d_out;

    int N = in_sizes[0] / D;
    int E = in_sizes[1];

    int prepWork = N * D / 16 + 3 * D * D / 8 + N;
    prep<<<(prepWork + 255) / 256, 256>>>(feat, weight, loopw, N);

    dim3 grid((N + BM - 1) / BM, 7);   // y<6: gemm slices, y==6: edge binning
    gemm16<<<grid, 256>>>(src, dst, etypes, E, N);

    int agg_blocks = (N + 3) / 4;
    aggregate<<<agg_blocks, 256>>>(bias, out, N);
}

// round 12
// speedup vs baseline: 1.1247x; 1.1247x over previous
#include <cuda_runtime.h>
#include <cuda_fp16.h>

#define D       128
#define NMAX    50000
#define CAP     64

#define BM 128
#define BN 64
#define BK 32
#define STAGES 3
#define ASTR 40    // A smem row stride (halfs): 80B -> ldmatrix conflict-free
#define BSTRB 72   // B smem row stride (halfs): 144B -> ldmatrix conflict-free

// Scratch: fp16 feat, fp16 pre-scaled weights [3][128][128], fp16 h_rel,
// fp16 loop message, per-node counters, edge buckets.
__device__ __half   g_feat16[(size_t)NMAX * D];
__device__ __half   g_w16[3 * D * D];
__device__ __half   g_hrel[2ull * NMAX * D];
__device__ __half   g_loop16[(size_t)NMAX * D];
__device__ int      g_cnt[NMAX];
__device__ unsigned g_bucket[(size_t)NMAX * CAP];

static __device__ __forceinline__ void cp16(unsigned d, const void* s, bool pred) {
    asm volatile("cp.async.cg.shared.global [%0], [%1], 16, %2;"
                 :: "r"(d), "l"(s), "r"(pred ? 16 : 0));
}
static __device__ __forceinline__ void cp_commit() {
    asm volatile("cp.async.commit_group;");
}
template <int NN> static __device__ __forceinline__ void cp_wait() {
    asm volatile("cp.async.wait_group %0;" :: "n"(NN));
}

static __device__ __forceinline__ void ldsm_x4(
    unsigned& r0, unsigned& r1, unsigned& r2, unsigned& r3, unsigned addr)
{
    asm volatile("ldmatrix.sync.aligned.m8n8.x4.shared.b16 {%0,%1,%2,%3}, [%4];"
                 : "=r"(r0), "=r"(r1), "=r"(r2), "=r"(r3) : "r"(addr));
}
static __device__ __forceinline__ void ldsm_x4_t(
    unsigned& r0, unsigned& r1, unsigned& r2, unsigned& r3, unsigned addr)
{
    asm volatile("ldmatrix.sync.aligned.m8n8.x4.trans.shared.b16 {%0,%1,%2,%3}, [%4];"
                 : "=r"(r0), "=r"(r1), "=r"(r2), "=r"(r3) : "r"(addr));
}
static __device__ __forceinline__ void mma_f16(
    float c[4], const unsigned a[4], unsigned b0, unsigned b1)
{
    asm volatile(
        "mma.sync.aligned.m16n8k16.row.col.f32.f16.f16.f32 "
        "{%0,%1,%2,%3}, {%4,%5,%6,%7}, {%8,%9}, {%0,%1,%2,%3};"
        : "+f"(c[0]), "+f"(c[1]), "+f"(c[2]), "+f"(c[3])
        : "r"(a[0]), "r"(a[1]), "r"(a[2]), "r"(a[3]), "r"(b0), "r"(b1));
}

// prep: feat -> fp16 (streaming fp32 reads); weights -> pre-scaled fp16
// [W0|W1|loopW]; zero counters. 8 elements per thread (round-10 config).
__global__ __launch_bounds__(256) void prep(
    const float* __restrict__ feat,
    const float* __restrict__ weight,
    const float* __restrict__ loopw,
    int N)
{
    const float s = 0.70710678118654752440f;
    int idx = blockIdx.x * blockDim.x + threadIdx.x;
    int featChunks = N * D / 8;
    if (idx < featChunks) {
        const float* fp = &feat[(size_t)idx * 8];
        float4 v0 = __ldcs((const float4*)fp);
        float4 v1 = __ldcs((const float4*)(fp + 4));
        __half2 h[4];
        h[0] = __floats2half2_rn(v0.x, v0.y);
        h[1] = __floats2half2_rn(v0.z, v0.w);
        h[2] = __floats2half2_rn(v1.x, v1.y);
        h[3] = __floats2half2_rn(v1.z, v1.w);
        *(uint4*)&g_feat16[(size_t)idx * 8] = *(uint4*)h;
    } else if (idx < featChunks + 3 * D * D / 8) {
        int j = idx - featChunks;
        const float* srcp = (j < 2 * D * D / 8)
            ? &weight[(size_t)j * 8]
            : &loopw[(size_t)(j - 2 * D * D / 8) * 8];
        float4 v0 = *(const float4*)srcp;
        float4 v1 = *(const float4*)(srcp + 4);
        __half2 h[4];
        h[0] = __floats2half2_rn(s * v0.x, s * v0.y);
        h[1] = __floats2half2_rn(s * v0.z, s * v0.w);
        h[2] = __floats2half2_rn(s * v1.x, s * v1.y);
        h[3] = __floats2half2_rn(s * v1.z, s * v1.w);
        *(uint4*)&g_w16[(size_t)j * 8] = *(uint4*)h;
    } else if (idx < featChunks + 3 * D * D / 8 + N) {
        g_cnt[idx - featChunks - 3 * D * D / 8] = 0;
    }
}

// Fused kernel:
//   blockIdx.y < 6 : fp16 tensor-core GEMM, 3-stage cp.async pipeline.
//       cb = y>>1 selects weight plane; (y&1) selects 64-col half.
//       cb 0,1: h_rel[cb] (fp16); cb 2: loop message (fp16).
//   blockIdx.y == 6: edge binning (grid-stride), concurrent with GEMM.
// 4 blocks/SM (64-reg cap) for deeper latency hiding in the mma mainloop.
__global__ __launch_bounds__(256, 4) void gemm16(
    const int* __restrict__ src,
    const int* __restrict__ dst,
    const int* __restrict__ et,
    int E, int N)
{
    __shared__ __align__(16) __half As[STAGES][BM][ASTR];   // [m][k]
    __shared__ __align__(16) __half Bs[STAGES][BK][BSTRB];  // [k][n]

    const int tid  = threadIdx.x;

    if (blockIdx.y == 6) {
        int stride = gridDim.x * 256;
        for (int e = blockIdx.x * 256 + tid; e < E; e += stride) {
            int s = __ldg(&src[e]);
            int d = __ldg(&dst[e]);
            int r = __ldg(&et[e]);
            int pos = atomicAdd(&g_cnt[d], 1);
            if (pos < CAP) {
                g_bucket[(size_t)d * CAP + pos] = (unsigned)(r * N + s);
            } else {
                const __half2* row =
                    (const __half2*)&g_hrel[((size_t)r * N + (size_t)s) * D];
                __half2* lp = (__half2*)&g_loop16[(size_t)d * D];
                for (int i = 0; i < D / 2; i++)
                    atomicAdd(&lp[i], row[i]);
            }
        }
        return;
    }

    const int lane = tid & 31;
    const int wid  = tid >> 5;
    const int g    = lane >> 2;
    const int t    = lane & 3;
    const int wm   = (wid & 3) * 32;
    const int wn   = (wid >> 2) * 32;
    const int m0   = blockIdx.x * BM;
    const int cb   = blockIdx.y >> 1;
    const int n0   = (blockIdx.y & 1) * BN;

    const __half* Bg = g_w16 + (size_t)cb * D * D;

    const int arow = tid >> 1;
    const int aoff = (tid & 1) * 16;
    const int gm_a = m0 + arow;
    const bool apred = gm_a < N;
    const int brow = tid >> 3;
    const int boff = (tid & 7) * 8;

    const unsigned asA = (unsigned)__cvta_generic_to_shared(&As[0][arow][aoff]);
    const unsigned asB = (unsigned)__cvta_generic_to_shared(&Bs[0][brow][boff]);
    const unsigned aStage = BM * ASTR * 2;
    const unsigned bStage = BK * BSTRB * 2;

    const int a_m = lane & 15, a_k = (lane >> 4) * 8;
    const int b_k = lane & 15, b_n = (lane >> 4) * 8;
    const unsigned asL = (unsigned)__cvta_generic_to_shared(&As[0][wm + a_m][a_k]);
    const unsigned bsL = (unsigned)__cvta_generic_to_shared(&Bs[0][b_k][wn + b_n]);

    float acc[2][4][4];
#pragma unroll
    for (int i = 0; i < 2; i++)
#pragma unroll
        for (int j = 0; j < 4; j++)
#pragma unroll
            for (int q = 0; q < 4; q++) acc[i][j][q] = 0.f;

    auto issue = [&](int p, int st) {
        const __half* gA = &g_feat16[(size_t)gm_a * D + p * BK + aoff];
        cp16(asA + st * aStage, gA, apred);
        cp16(asA + st * aStage + 16, gA + 8, apred);
        const __half* gB = &Bg[(size_t)(p * BK + brow) * D + n0 + boff];
        cp16(asB + st * bStage, gB, true);
        cp_commit();
    };

    issue(0, 0);
    issue(1, 1);

#pragma unroll
    for (int p = 0; p < 4; p++) {
        if (p < 3) { cp_wait<1>(); } else { cp_wait<0>(); }
        __syncthreads();
        if (p < 2) issue(p + 2, (p + 2) % STAGES);

        const int st = p % STAGES;
        const unsigned aB = asL + st * aStage;
        const unsigned bB = bsL + st * bStage;
#pragma unroll
        for (int kk = 0; kk < BK; kk += 16) {
            unsigned a[2][4];
            ldsm_x4(a[0][0], a[0][1], a[0][2], a[0][3], aB + kk * 2);
            ldsm_x4(a[1][0], a[1][1], a[1][2], a[1][3], aB + 16 * ASTR * 2 + kk * 2);
#pragma unroll
            for (int q = 0; q < 2; q++) {
                unsigned bq[4];
                ldsm_x4_t(bq[0], bq[1], bq[2], bq[3],
                          bB + kk * BSTRB * 2 + q * 16 * 2);
                mma_f16(acc[0][2 * q],     a[0], bq[0], bq[1]);
                mma_f16(acc[1][2 * q],     a[1], bq[0], bq[1]);
                mma_f16(acc[0][2 * q + 1], a[0], bq[2], bq[3]);
                mma_f16(acc[1][2 * q + 1], a[1], bq[2], bq[3]);
            }
        }
    }

    __half* dstb = (cb < 2) ? &g_hrel[(size_t)cb * N * D] : g_loop16;
#pragma unroll
    for (int mt = 0; mt < 2; mt++) {
        int gm_lo = m0 + wm + mt * 16 + g;
        int gm_hi = gm_lo + 8;
#pragma unroll
        for (int nt = 0; nt < 4; nt++) {
            int col = n0 + wn + nt * 8 + 2 * t;
            if (gm_lo < N)
                *(__half2*)&dstb[(size_t)gm_lo * D + col] =
                    __floats2half2_rn(acc[mt][nt][0], acc[mt][nt][1]);
            if (gm_hi < N)
                *(__half2*)&dstb[(size_t)gm_hi * D + col] =
                    __floats2half2_rn(acc[mt][nt][2], acc[mt][nt][3]);
        }
    }
}

// One warp per node: out = bias + loop16 + sum(bucketed messages).
// Direct per-entry index loads (streaming), cached uint2 gathers (rows are
// reused ~5x across nodes), fp32 accumulation, streaming output store.
__global__ __launch_bounds__(256) void aggregate(
    const float* __restrict__ bias,
    float* __restrict__ out, int N)
{
    int n = (blockIdx.x * 256 + threadIdx.x) >> 5;
    if (n >= N) return;
    int lane = threadIdx.x & 31;
    int cnt = g_cnt[n];
    if (cnt > CAP) cnt = CAP;

    uint2 lv = __ldg((const uint2*)&g_loop16[(size_t)n * D + lane * 4]);
    float2 l0 = __half22float2(*(__half2*)&lv.x);
    float2 l1 = __half22float2(*(__half2*)&lv.y);
    float4 bv = __ldg((const float4*)&bias[lane * 4]);
    float4 acc = make_float4(l0.x + bv.x, l0.y + bv.y, l1.x + bv.z, l1.y + bv.w);

    const unsigned* bk = &g_bucket[(size_t)n * CAP];
#pragma unroll 8
    for (int j = 0; j < cnt; j++) {
        unsigned idx = __ldcs(&bk[j]);
        uint2 hv = __ldg((const uint2*)&g_hrel[(size_t)idx * D + lane * 4]);
        float2 f0 = __half22float2(*(__half2*)&hv.x);
        float2 f1 = __half22float2(*(__half2*)&hv.y);
        acc.x += f0.x; acc.y += f0.y; acc.z += f1.x; acc.w += f1.y;
    }
    __stcs((float4*)&out[(size_t)n * D + lane * 4], acc);
}

extern "C" void kernel_launch(void* const* d_in, const int* in_sizes, int n_in,
                              void* d_out, int out_size) {
    const float* feat   = (const float*)d_in[0];
    const int*   src    = (const int*)d_in[1];
    const int*   dst    = (const int*)d_in[2];
    const int*   etypes = (const int*)d_in[3];
    const float* weight = (const float*)d_in[4];
    const float* loopw  = (const float*)d_in[5];
    const float* bias   = (const float*)d_in[6];
    float* out = (float*)d_out;

    int N = in_sizes[0] / D;
    int E = in_sizes[1];

    int prepWork = N * D / 8 + 3 * D * D / 8 + N;
    prep<<<(prepWork + 255) / 256, 256>>>(feat, weight, loopw, N);

    dim3 grid((N + BM - 1) / BM, 7);   // y<6: gemm slices, y==6: edge binning
    gemm16<<<grid, 256>>>(src, dst, etypes, E, N);

    int agg_blocks = (N * 32 + 255) / 256;
    aggregate<<<agg_blocks, 256>>>(bias, out, N);
}